// round 5
// baseline (speedup 1.0000x reference)
#include <cuda_runtime.h>
#include <cuda_fp16.h>
#include <math.h>

#define NN 100000
#define EE 3200000
#define NB 98   // (NN+1023)/1024 blocks for the fused scan

typedef unsigned long long ull;

// ---------------- scratch (__device__ globals; no allocs allowed) ----------------
__device__ __half2 g_hh[(size_t)NN * 32];  // 12.8 MB  (h * dinv[row], fp16)
__device__ float   g_hf[(size_t)NN * 64];  // 25.6 MB  (agg output, fp32)
__device__ int     g_counts[NN];
__device__ int     g_offsets[NN + 1];
__device__ int     g_cursor[NN];
__device__ int     g_csr[EE];              // 12.8 MB (src sorted by dst)
__device__ float   g_dinv[NN];
__device__ int     g_bsums[NB];
__device__ int     g_scan_ready;
__device__ int     g_is64;

// ---------------- packed f32x2 helpers ----------------
__device__ __forceinline__ void ffma2(ull& d, ull a, ull b) {
    asm("fma.rn.f32x2 %0, %1, %2, %0;" : "+l"(d) : "l"(a), "l"(b));
}
__device__ __forceinline__ ull bcast2(float x) {
    unsigned u = __float_as_uint(x);
    return ((ull)u << 32) | (ull)u;
}

// ---------------- zero counts + dtype detect + scan-flag reset (fused) ----------------
__global__ void k_zero_detect(const void* edges) {
    int i = blockIdx.x * blockDim.x + threadIdx.x;
    if (i < NN) g_counts[i] = 0;
    if (i == 0) {
        g_scan_ready = 0;
        const unsigned* w = (const unsigned*)edges;
        int is64 = 1;
        #pragma unroll
        for (int k = 1; k < 64; k += 2) {
            if (w[k] != 0u) { is64 = 0; break; }
        }
        g_is64 = is64;
    }
}

// ---------------- in-degree histogram over dst (2 edges / thread) ----------------
__global__ void k_hist(const void* edges) {
    int e2 = blockIdx.x * blockDim.x + threadIdx.x;
    if (e2 >= EE / 2) return;
    int is64 = g_is64;
    int d0, d1;
    if (is64) {
        longlong2 q = ((const longlong2*)edges)[EE / 2 + e2];
        d0 = (int)q.x; d1 = (int)q.y;
    } else {
        int2 q = ((const int2*)edges)[EE / 2 + e2];
        d0 = q.x; d1 = q.y;
    }
    atomicAdd(&g_counts[d0], 1);
    atomicAdd(&g_counts[d1], 1);
}

// ---------------- fused scan: block scan + grid barrier + carry + apply ----------------
__global__ __launch_bounds__(1024)
void k_scanall() {
    __shared__ int wsum[32];
    __shared__ int s_carry;
    int t = threadIdx.x, lane = t & 31, wid = t >> 5;
    int bid = blockIdx.x;
    int idx = bid * 1024 + t;
    int v = (idx < NN) ? g_counts[idx] : 0;

    // block-wide inclusive scan of v -> x
    int x = v;
    #pragma unroll
    for (int off = 1; off < 32; off <<= 1) {
        int y = __shfl_up_sync(0xffffffffu, x, off);
        if (lane >= off) x += y;
    }
    if (lane == 31) wsum[wid] = x;
    __syncthreads();
    if (wid == 0) {
        int s = wsum[lane];
        #pragma unroll
        for (int off = 1; off < 32; off <<= 1) {
            int y = __shfl_up_sync(0xffffffffu, s, off);
            if (lane >= off) s += y;
        }
        wsum[lane] = s;
    }
    __syncthreads();
    int warp_excl = (wid > 0) ? wsum[wid - 1] : 0;
    int block_total = wsum[31];
    x += warp_excl;   // inclusive within block

    // publish block total, then barrier
    if (t == 0) {
        g_bsums[bid] = block_total;
        __threadfence();
        atomicAdd(&g_scan_ready, 1);
    }
    if (wid == 0) {
        if (lane == 0) {
            while (atomicAdd(&g_scan_ready, 0) < NB) { }
        }
        __syncwarp();
        __threadfence();
        int c = 0;
        for (int i = lane; i < bid; i += 32) c += g_bsums[i];
        #pragma unroll
        for (int off = 16; off > 0; off >>= 1)
            c += __shfl_down_sync(0xffffffffu, c, off);
        if (lane == 0) s_carry = c;
    }
    __syncthreads();

    int carry = s_carry;
    if (idx < NN) {
        int excl = carry + x - v;
        g_offsets[idx] = excl;
        g_cursor[idx]  = excl;
        g_dinv[idx]    = rsqrtf((float)(v + 1));
    }
    if (bid == NB - 1 && t == 0) g_offsets[NN] = carry + block_total;
}

// ---------------- CSR fill (2 edges / thread) ----------------
__global__ void k_fill(const void* edges) {
    int e2 = blockIdx.x * blockDim.x + threadIdx.x;
    if (e2 >= EE / 2) return;
    int is64 = g_is64;
    int s0, s1, d0, d1;
    if (is64) {
        longlong2 qs = ((const longlong2*)edges)[e2];
        longlong2 qd = ((const longlong2*)edges)[EE / 2 + e2];
        s0 = (int)qs.x; s1 = (int)qs.y;
        d0 = (int)qd.x; d1 = (int)qd.y;
    } else {
        int2 qs = ((const int2*)edges)[e2];
        int2 qd = ((const int2*)edges)[EE / 2 + e2];
        s0 = qs.x; s1 = qs.y;
        d0 = qd.x; d1 = qd.y;
    }
    g_csr[atomicAdd(&g_cursor[d0], 1)] = s0;
    g_csr[atomicAdd(&g_cursor[d1], 1)] = s1;
}

// ---------------- GEMM: H'[r] = (X[r] @ W) * dinv[r], output fp16 ----------------
template <int K>
__global__ __launch_bounds__(256)
void k_gemm(const float* __restrict__ X, const float* __restrict__ W,
            __half2* __restrict__ C) {
    __shared__ float Ws[K * 64];
    for (int i = threadIdx.x; i < K * 16; i += 256) {
        ((float4*)Ws)[i] = ((const float4*)W)[i];
    }
    __syncthreads();
    int r = blockIdx.x * 256 + threadIdx.x;
    if (r >= NN) return;

    ull acc[32];
    #pragma unroll
    for (int j = 0; j < 32; j++) acc[j] = 0ull;

    const float4* xr = (const float4*)(X + (size_t)r * K);
    #pragma unroll 2
    for (int k4 = 0; k4 < K / 4; k4++) {
        float4 xv = xr[k4];
        float xk[4] = {xv.x, xv.y, xv.z, xv.w};
        #pragma unroll
        for (int kk = 0; kk < 4; kk++) {
            const ull* wr = (const ull*)&Ws[(k4 * 4 + kk) * 64];
            ull xs2 = bcast2(xk[kk]);
            #pragma unroll
            for (int j = 0; j < 32; j++) ffma2(acc[j], xs2, wr[j]);
        }
    }
    float dv = g_dinv[r];
    __half2 hv[32];
    #pragma unroll
    for (int j = 0; j < 32; j++) {
        float2 f = *(float2*)&acc[j];
        hv[j] = __floats2half2_rn(f.x * dv, f.y * dv);
    }
    uint4* cr = (uint4*)(C + (size_t)r * 32);
    const uint4* hv4 = (const uint4*)hv;
    #pragma unroll
    for (int j = 0; j < 8; j++) cr[j] = hv4[j];
}

// ---------------- aggregation: out[v] = dinv[v]*(sum_e h'[src] + h'[v]) + b
// 2 nodes per warp (16 lanes each, 8B/lane); shfl-16 index broadcast; 4 rows in flight.
__device__ __forceinline__ void acc8(float4& a, uint2 q) {
    float2 f0 = __half22float2(*(__half2*)&q.x);
    float2 f1 = __half22float2(*(__half2*)&q.y);
    a.x += f0.x; a.y += f0.y; a.z += f1.x; a.w += f1.y;
}

__global__ __launch_bounds__(256)
void k_agg(const uint2* __restrict__ H2, const float* __restrict__ b,
           float* __restrict__ out) {
    int w = threadIdx.x >> 5;
    int lane = threadIdx.x & 31;
    int half = lane >> 4;
    int sub = lane & 15;
    unsigned hmask = half ? 0xFFFF0000u : 0x0000FFFFu;
    int v = blockIdx.x * 16 + w * 2 + half;
    if (v >= NN) return;
    int beg = g_offsets[v];
    int end = g_offsets[v + 1];
    float dv = g_dinv[v];

    float4 a0 = {0.f, 0.f, 0.f, 0.f};
    float4 a1 = {0.f, 0.f, 0.f, 0.f};
    float4 a2 = {0.f, 0.f, 0.f, 0.f};
    float4 a3 = {0.f, 0.f, 0.f, 0.f};

    for (int e = beg; e < end; e += 16) {
        int cnt = min(16, end - e);
        int s = (sub < cnt) ? g_csr[e + sub] : 0;
        int i = 0;
        for (; i + 4 <= cnt; i += 4) {
            int s0 = __shfl_sync(hmask, s, i + 0, 16);
            int s1 = __shfl_sync(hmask, s, i + 1, 16);
            int s2 = __shfl_sync(hmask, s, i + 2, 16);
            int s3 = __shfl_sync(hmask, s, i + 3, 16);
            uint2 q0 = H2[(size_t)s0 * 16 + sub];
            uint2 q1 = H2[(size_t)s1 * 16 + sub];
            uint2 q2 = H2[(size_t)s2 * 16 + sub];
            uint2 q3 = H2[(size_t)s3 * 16 + sub];
            acc8(a0, q0); acc8(a1, q1); acc8(a2, q2); acc8(a3, q3);
        }
        for (; i < cnt; i++) {
            int si = __shfl_sync(hmask, s, i, 16);
            uint2 q = H2[(size_t)si * 16 + sub];
            acc8(a0, q);
        }
    }
    uint2 qv = H2[(size_t)v * 16 + sub];
    acc8(a0, qv);

    float4 r;
    r.x = a0.x + a1.x + a2.x + a3.x;
    r.y = a0.y + a1.y + a2.y + a3.y;
    r.z = a0.z + a1.z + a2.z + a3.z;
    r.w = a0.w + a1.w + a2.w + a3.w;
    float4 bb = ((const float4*)b)[sub];
    float4 o;
    o.x = r.x * dv + bb.x;
    o.y = r.y * dv + bb.y;
    o.z = r.z * dv + bb.z;
    o.w = r.w * dv + bb.w;
    ((float4*)out)[(size_t)v * 16 + sub] = o;
}

// ---------------- fused MLP head, packed f32x2 FMA ----------------
__global__ __launch_bounds__(128)
void k_mlp(const float* __restrict__ h,
           const float* __restrict__ lw1, const float* __restrict__ lb1,
           const float* __restrict__ lw2, const float* __restrict__ lb2,
           const float* __restrict__ lw3, const float* __restrict__ lb3,
           float* __restrict__ out) {
    __shared__ float s_w1[64 * 64];
    __shared__ float s_w2[64 * 32];
    __shared__ float s_w3[32];
    __shared__ float s_b1[64];
    __shared__ float s_b2[32];
    __shared__ float s_b3;
    int t = threadIdx.x;
    for (int i = t; i < 64 * 16; i += 128) ((float4*)s_w1)[i] = ((const float4*)lw1)[i];
    for (int i = t; i < 64 * 8;  i += 128) ((float4*)s_w2)[i] = ((const float4*)lw2)[i];
    if (t < 32) s_w3[t] = lw3[t];
    if (t < 64) s_b1[t] = lb1[t];
    if (t < 32) s_b2[t] = lb2[t];
    if (t == 0) s_b3 = lb3[0];
    __syncthreads();

    int v = blockIdx.x * 128 + t;
    if (v >= NN) return;

    float in[64];
    const float4* hr = (const float4*)(h + (size_t)v * 64);
    #pragma unroll
    for (int i = 0; i < 16; i++) {
        float4 q = hr[i];
        in[4 * i + 0] = q.x; in[4 * i + 1] = q.y;
        in[4 * i + 2] = q.z; in[4 * i + 3] = q.w;
    }

    // layer1: 64 -> 64
    ull a1[32];
    #pragma unroll
    for (int j = 0; j < 32; j++) a1[j] = ((const ull*)s_b1)[j];
    #pragma unroll
    for (int k = 0; k < 64; k++) {
        ull xs2 = bcast2(in[k]);
        const ull* wr = (const ull*)&s_w1[k * 64];
        #pragma unroll
        for (int j = 0; j < 32; j++) ffma2(a1[j], xs2, wr[j]);
    }
    float t1[64];
    #pragma unroll
    for (int j = 0; j < 32; j++) {
        float2 f = *(float2*)&a1[j];
        t1[2 * j]     = fmaxf(f.x, 0.f);
        t1[2 * j + 1] = fmaxf(f.y, 0.f);
    }

    // layer2: 64 -> 32
    ull a2[16];
    #pragma unroll
    for (int j = 0; j < 16; j++) a2[j] = ((const ull*)s_b2)[j];
    #pragma unroll
    for (int k = 0; k < 64; k++) {
        ull xs2 = bcast2(t1[k]);
        const ull* wr = (const ull*)&s_w2[k * 32];
        #pragma unroll
        for (int j = 0; j < 16; j++) ffma2(a2[j], xs2, wr[j]);
    }
    float t2[32];
    #pragma unroll
    for (int j = 0; j < 16; j++) {
        float2 f = *(float2*)&a2[j];
        t2[2 * j]     = fmaxf(f.x, 0.f);
        t2[2 * j + 1] = fmaxf(f.y, 0.f);
    }

    // layer3: 32 -> 1
    float o = s_b3;
    #pragma unroll
    for (int k = 0; k < 32; k++) o += t2[k] * s_w3[k];
    out[v] = o;
}

// ---------------- launcher ----------------
extern "C" void kernel_launch(void* const* d_in, const int* in_sizes, int n_in,
                              void* d_out, int out_size) {
    const float* x   = (const float*)d_in[0];
    const void*  edg = d_in[1];
    const float* W1  = (const float*)d_in[2];
    const float* b1  = (const float*)d_in[3];
    const float* W2  = (const float*)d_in[4];
    const float* b2  = (const float*)d_in[5];
    const float* lw1 = (const float*)d_in[6];
    const float* lb1 = (const float*)d_in[7];
    const float* lw2 = (const float*)d_in[8];
    const float* lb2 = (const float*)d_in[9];
    const float* lw3 = (const float*)d_in[10];
    const float* lb3 = (const float*)d_in[11];
    float* out = (float*)d_out;

    __half2* hh; cudaGetSymbolAddress((void**)&hh, g_hh);
    float*   hf; cudaGetSymbolAddress((void**)&hf, g_hf);

    const int E2B = (EE / 2 + 255) / 256;

    k_zero_detect<<<(NN + 1023) / 1024, 1024>>>(edg);   // 0
    k_hist<<<E2B, 256>>>(edg);                          // 1
    k_scanall<<<NB, 1024>>>();                          // 2
    k_fill<<<E2B, 256>>>(edg);                          // 3  <- profiled launch

    // conv1: hh = (x @ W1) * dinv ; hf = aggregate(hh) + b1
    k_gemm<128><<<(NN + 255) / 256, 256>>>(x, W1, hh);  // 4
    k_agg<<<(NN + 15) / 16, 256>>>((const uint2*)hh, b1, hf);   // 5

    // conv2: hh = (hf @ W2) * dinv ; hf = aggregate(hh) + b2
    k_gemm<64><<<(NN + 255) / 256, 256>>>(hf, W2, hh);  // 6
    k_agg<<<(NN + 15) / 16, 256>>>((const uint2*)hh, b2, hf);   // 7

    // MLP head
    k_mlp<<<(NN + 127) / 128, 128>>>(hf, lw1, lb1, lw2, lb2, lw3, lb3, out);  // 8
}

// round 6
// speedup vs baseline: 1.0778x; 1.0778x over previous
#include <cuda_runtime.h>
#include <cuda_fp16.h>
#include <math.h>

#define NN 100000
#define EE 3200000
#define NB 98   // (NN+1023)/1024 blocks for the fused scan

typedef unsigned long long ull;

// ---------------- scratch (__device__ globals; no allocs allowed) ----------------
__device__ __half2 g_hh[(size_t)(NN + 1) * 32]; // 12.8 MB; row NN = zeros (pad row)
__device__ float   g_hf[(size_t)NN * 64];       // 25.6 MB  (agg output, fp32)
__device__ int     g_counts[NN];
__device__ int     g_offsets[NN + 1];
__device__ int     g_cursor[NN];
__device__ int     g_csr[EE];                   // 12.8 MB (src sorted by dst)
__device__ float   g_dinv[NN];
__device__ int     g_bsums[NB];
__device__ int     g_scan_ready;
__device__ int     g_is64;

// ---------------- packed f32x2 helpers ----------------
__device__ __forceinline__ void ffma2(ull& d, ull a, ull b) {
    asm("fma.rn.f32x2 %0, %1, %2, %0;" : "+l"(d) : "l"(a), "l"(b));
}
__device__ __forceinline__ ull bcast2(float x) {
    unsigned u = __float_as_uint(x);
    return ((ull)u << 32) | (ull)u;
}

// ---------------- zero counts + dtype detect + pad-row + flag reset ----------------
__global__ void k_zero_detect(const void* edges) {
    int i = blockIdx.x * blockDim.x + threadIdx.x;
    if (i < NN) g_counts[i] = 0;
    if (i < 32) g_hh[(size_t)NN * 32 + i] = __half2half2(__ushort_as_half(0));
    if (i == 0) {
        g_scan_ready = 0;
        const unsigned* w = (const unsigned*)edges;
        int is64 = 1;
        #pragma unroll
        for (int k = 1; k < 64; k += 2) {
            if (w[k] != 0u) { is64 = 0; break; }
        }
        g_is64 = is64;
    }
}

// ---------------- in-degree histogram over dst (2 edges / thread) ----------------
__global__ void k_hist(const void* edges) {
    int e2 = blockIdx.x * blockDim.x + threadIdx.x;
    if (e2 >= EE / 2) return;
    int is64 = g_is64;
    int d0, d1;
    if (is64) {
        longlong2 q = ((const longlong2*)edges)[EE / 2 + e2];
        d0 = (int)q.x; d1 = (int)q.y;
    } else {
        int2 q = ((const int2*)edges)[EE / 2 + e2];
        d0 = q.x; d1 = q.y;
    }
    atomicAdd(&g_counts[d0], 1);
    atomicAdd(&g_counts[d1], 1);
}

// ---------------- fused scan: block scan + grid barrier + carry + apply ----------------
__global__ __launch_bounds__(1024)
void k_scanall() {
    __shared__ int wsum[32];
    __shared__ int s_carry;
    int t = threadIdx.x, lane = t & 31, wid = t >> 5;
    int bid = blockIdx.x;
    int idx = bid * 1024 + t;
    int v = (idx < NN) ? g_counts[idx] : 0;

    int x = v;
    #pragma unroll
    for (int off = 1; off < 32; off <<= 1) {
        int y = __shfl_up_sync(0xffffffffu, x, off);
        if (lane >= off) x += y;
    }
    if (lane == 31) wsum[wid] = x;
    __syncthreads();
    if (wid == 0) {
        int s = wsum[lane];
        #pragma unroll
        for (int off = 1; off < 32; off <<= 1) {
            int y = __shfl_up_sync(0xffffffffu, s, off);
            if (lane >= off) s += y;
        }
        wsum[lane] = s;
    }
    __syncthreads();
    int warp_excl = (wid > 0) ? wsum[wid - 1] : 0;
    int block_total = wsum[31];
    x += warp_excl;

    if (t == 0) {
        g_bsums[bid] = block_total;
        __threadfence();
        atomicAdd(&g_scan_ready, 1);
    }
    if (wid == 0) {
        if (lane == 0) {
            while (atomicAdd(&g_scan_ready, 0) < NB) { }
        }
        __syncwarp();
        __threadfence();
        int c = 0;
        for (int i = lane; i < bid; i += 32) c += g_bsums[i];
        #pragma unroll
        for (int off = 16; off > 0; off >>= 1)
            c += __shfl_down_sync(0xffffffffu, c, off);
        if (lane == 0) s_carry = c;
    }
    __syncthreads();

    int carry = s_carry;
    if (idx < NN) {
        int excl = carry + x - v;
        g_offsets[idx] = excl;
        g_cursor[idx]  = excl;
        g_dinv[idx]    = rsqrtf((float)(v + 1));
    }
    if (bid == NB - 1 && t == 0) g_offsets[NN] = carry + block_total;
}

// ---------------- CSR fill (2 edges / thread) ----------------
__global__ void k_fill(const void* edges) {
    int e2 = blockIdx.x * blockDim.x + threadIdx.x;
    if (e2 >= EE / 2) return;
    int is64 = g_is64;
    int s0, s1, d0, d1;
    if (is64) {
        longlong2 qs = ((const longlong2*)edges)[e2];
        longlong2 qd = ((const longlong2*)edges)[EE / 2 + e2];
        s0 = (int)qs.x; s1 = (int)qs.y;
        d0 = (int)qd.x; d1 = (int)qd.y;
    } else {
        int2 qs = ((const int2*)edges)[e2];
        int2 qd = ((const int2*)edges)[EE / 2 + e2];
        s0 = qs.x; s1 = qs.y;
        d0 = qd.x; d1 = qd.y;
    }
    g_csr[atomicAdd(&g_cursor[d0], 1)] = s0;
    g_csr[atomicAdd(&g_cursor[d1], 1)] = s1;
}

// ---------------- GEMM: H'[r] = (X[r] @ W) * dinv[r], output fp16 ----------------
template <int K>
__global__ __launch_bounds__(256)
void k_gemm(const float* __restrict__ X, const float* __restrict__ W,
            __half2* __restrict__ C) {
    __shared__ float Ws[K * 64];
    for (int i = threadIdx.x; i < K * 16; i += 256) {
        ((float4*)Ws)[i] = ((const float4*)W)[i];
    }
    __syncthreads();
    int r = blockIdx.x * 256 + threadIdx.x;
    if (r >= NN) return;

    ull acc[32];
    #pragma unroll
    for (int j = 0; j < 32; j++) acc[j] = 0ull;

    const float4* xr = (const float4*)(X + (size_t)r * K);
    #pragma unroll 2
    for (int k4 = 0; k4 < K / 4; k4++) {
        float4 xv = xr[k4];
        float xk[4] = {xv.x, xv.y, xv.z, xv.w};
        #pragma unroll
        for (int kk = 0; kk < 4; kk++) {
            const ull* wr = (const ull*)&Ws[(k4 * 4 + kk) * 64];
            ull xs2 = bcast2(xk[kk]);
            #pragma unroll
            for (int j = 0; j < 32; j++) ffma2(acc[j], xs2, wr[j]);
        }
    }
    float dv = g_dinv[r];
    __half2 hv[32];
    #pragma unroll
    for (int j = 0; j < 32; j++) {
        float2 f = *(float2*)&acc[j];
        hv[j] = __floats2half2_rn(f.x * dv, f.y * dv);
    }
    uint4* cr = (uint4*)(C + (size_t)r * 32);
    const uint4* hv4 = (const uint4*)hv;
    #pragma unroll
    for (int j = 0; j < 8; j++) cr[j] = hv4[j];
}

// ---------------- aggregation: out[v] = dinv[v]*(sum_e h'[src] + h'[v]) + b
// warp per node; lane loads 16B (8 channels); 4 edges per warp LDG; pad with zero row NN.
__device__ __forceinline__ void addq(float* a, uint4 q) {
    float2 f;
    f = __half22float2(*(__half2*)&q.x); a[0] += f.x; a[1] += f.y;
    f = __half22float2(*(__half2*)&q.y); a[2] += f.x; a[3] += f.y;
    f = __half22float2(*(__half2*)&q.z); a[4] += f.x; a[5] += f.y;
    f = __half22float2(*(__half2*)&q.w); a[6] += f.x; a[7] += f.y;
}

__global__ __launch_bounds__(256)
void k_agg(const uint4* __restrict__ H4, const float* __restrict__ b,
           float* __restrict__ out) {
    __shared__ int s_idx[8][32];
    int w = threadIdx.x >> 5;
    int lane = threadIdx.x & 31;
    int g = lane >> 3;     // edge slot within group-of-4
    int c = lane & 7;      // 16B chunk within 128B row
    int v = blockIdx.x * 8 + w;
    if (v >= NN) return;
    int beg = g_offsets[v];
    int end = g_offsets[v + 1];
    float dv = g_dinv[v];
    int* sw = s_idx[w];

    float accA[8] = {0.f, 0.f, 0.f, 0.f, 0.f, 0.f, 0.f, 0.f};
    float accB[8] = {0.f, 0.f, 0.f, 0.f, 0.f, 0.f, 0.f, 0.f};

    for (int e = beg; e < end; e += 32) {
        int cnt = min(32, end - e);
        sw[lane] = (lane < cnt) ? g_csr[e + lane] : NN;
        __syncwarp();
        int iters = (cnt + 3) >> 2;
        int k = 0;
        for (; k + 2 <= iters; k += 2) {
            int i0 = sw[k * 4 + g];
            int i1 = sw[k * 4 + 4 + g];
            uint4 q0 = H4[(size_t)i0 * 8 + c];
            uint4 q1 = H4[(size_t)i1 * 8 + c];
            addq(accA, q0);
            addq(accB, q1);
        }
        if (k < iters) {
            int i0 = sw[k * 4 + g];
            uint4 q0 = H4[(size_t)i0 * 8 + c];
            addq(accA, q0);
        }
        __syncwarp();
    }

    // self-loop term: add row v exactly once (group 0 only)
    if (g == 0) {
        uint4 qv = H4[(size_t)v * 8 + c];
        addq(accA, qv);
    }

    // merge + cross-group butterfly reduction (groups differ in bit3/bit4 of lane)
    #pragma unroll
    for (int j = 0; j < 8; j++) {
        float a = accA[j] + accB[j];
        a += __shfl_xor_sync(0xffffffffu, a, 8);
        a += __shfl_xor_sync(0xffffffffu, a, 16);
        accA[j] = a;
    }

    // lane writes channels [8c + 2g, 8c + 2g + 1]
    int ch = 8 * c + 2 * g;
    float2 bb = *(const float2*)(b + ch);
    float2 o;
    o.x = accA[2 * g]     * dv + bb.x;
    o.y = accA[2 * g + 1] * dv + bb.y;
    *(float2*)(out + (size_t)v * 64 + ch) = o;
}

// ---------------- fused MLP head, packed f32x2 FMA ----------------
__global__ __launch_bounds__(128)
void k_mlp(const float* __restrict__ h,
           const float* __restrict__ lw1, const float* __restrict__ lb1,
           const float* __restrict__ lw2, const float* __restrict__ lb2,
           const float* __restrict__ lw3, const float* __restrict__ lb3,
           float* __restrict__ out) {
    __shared__ float s_w1[64 * 64];
    __shared__ float s_w2[64 * 32];
    __shared__ float s_w3[32];
    __shared__ float s_b1[64];
    __shared__ float s_b2[32];
    __shared__ float s_b3;
    int t = threadIdx.x;
    for (int i = t; i < 64 * 16; i += 128) ((float4*)s_w1)[i] = ((const float4*)lw1)[i];
    for (int i = t; i < 64 * 8;  i += 128) ((float4*)s_w2)[i] = ((const float4*)lw2)[i];
    if (t < 32) s_w3[t] = lw3[t];
    if (t < 64) s_b1[t] = lb1[t];
    if (t < 32) s_b2[t] = lb2[t];
    if (t == 0) s_b3 = lb3[0];
    __syncthreads();

    int v = blockIdx.x * 128 + t;
    if (v >= NN) return;

    float in[64];
    const float4* hr = (const float4*)(h + (size_t)v * 64);
    #pragma unroll
    for (int i = 0; i < 16; i++) {
        float4 q = hr[i];
        in[4 * i + 0] = q.x; in[4 * i + 1] = q.y;
        in[4 * i + 2] = q.z; in[4 * i + 3] = q.w;
    }

    // layer1: 64 -> 64
    ull a1[32];
    #pragma unroll
    for (int j = 0; j < 32; j++) a1[j] = ((const ull*)s_b1)[j];
    #pragma unroll
    for (int k = 0; k < 64; k++) {
        ull xs2 = bcast2(in[k]);
        const ull* wr = (const ull*)&s_w1[k * 64];
        #pragma unroll
        for (int j = 0; j < 32; j++) ffma2(a1[j], xs2, wr[j]);
    }
    float t1[64];
    #pragma unroll
    for (int j = 0; j < 32; j++) {
        float2 f = *(float2*)&a1[j];
        t1[2 * j]     = fmaxf(f.x, 0.f);
        t1[2 * j + 1] = fmaxf(f.y, 0.f);
    }

    // layer2: 64 -> 32
    ull a2[16];
    #pragma unroll
    for (int j = 0; j < 16; j++) a2[j] = ((const ull*)s_b2)[j];
    #pragma unroll
    for (int k = 0; k < 64; k++) {
        ull xs2 = bcast2(t1[k]);
        const ull* wr = (const ull*)&s_w2[k * 32];
        #pragma unroll
        for (int j = 0; j < 16; j++) ffma2(a2[j], xs2, wr[j]);
    }
    float t2[32];
    #pragma unroll
    for (int j = 0; j < 16; j++) {
        float2 f = *(float2*)&a2[j];
        t2[2 * j]     = fmaxf(f.x, 0.f);
        t2[2 * j + 1] = fmaxf(f.y, 0.f);
    }

    // layer3: 32 -> 1
    float o = s_b3;
    #pragma unroll
    for (int k = 0; k < 32; k++) o += t2[k] * s_w3[k];
    out[v] = o;
}

// ---------------- launcher ----------------
extern "C" void kernel_launch(void* const* d_in, const int* in_sizes, int n_in,
                              void* d_out, int out_size) {
    const float* x   = (const float*)d_in[0];
    const void*  edg = d_in[1];
    const float* W1  = (const float*)d_in[2];
    const float* b1  = (const float*)d_in[3];
    const float* W2  = (const float*)d_in[4];
    const float* b2  = (const float*)d_in[5];
    const float* lw1 = (const float*)d_in[6];
    const float* lb1 = (const float*)d_in[7];
    const float* lw2 = (const float*)d_in[8];
    const float* lb2 = (const float*)d_in[9];
    const float* lw3 = (const float*)d_in[10];
    const float* lb3 = (const float*)d_in[11];
    float* out = (float*)d_out;

    __half2* hh; cudaGetSymbolAddress((void**)&hh, g_hh);
    float*   hf; cudaGetSymbolAddress((void**)&hf, g_hf);

    const int E2B = (EE / 2 + 255) / 256;

    k_zero_detect<<<(NN + 1023) / 1024, 1024>>>(edg);   // 0
    k_hist<<<E2B, 256>>>(edg);                          // 1
    k_scanall<<<NB, 1024>>>();                          // 2
    k_fill<<<E2B, 256>>>(edg);                          // 3  <- profiled launch

    // conv1: hh = (x @ W1) * dinv ; hf = aggregate(hh) + b1
    k_gemm<128><<<(NN + 255) / 256, 256>>>(x, W1, hh);              // 4
    k_agg<<<(NN + 7) / 8, 256>>>((const uint4*)hh, b1, hf);         // 5

    // conv2: hh = (hf @ W2) * dinv ; hf = aggregate(hh) + b2
    k_gemm<64><<<(NN + 255) / 256, 256>>>(hf, W2, hh);              // 6
    k_agg<<<(NN + 7) / 8, 256>>>((const uint4*)hh, b2, hf);         // 7

    // MLP head
    k_mlp<<<(NN + 127) / 128, 128>>>(hf, lw1, lb1, lw2, lb2, lw3, lb3, out);  // 8
}